// round 3
// baseline (speedup 1.0000x reference)
#include <cuda_runtime.h>
#include <cstdint>

// Problem constants
#define B_DIM   32
#define T_DIM   8192
#define KD      128          // feature dim (K of the fused GEMM)
#define ND      128          // hidden/output dim (N)
#define R_TOTAL (B_DIM * T_DIM)   // 262144 rows (M of the fused GEMM)
#define EPS_F   1e-10f

// Fused-GEMM tiling
#define BM 128
#define BK 32
#define NCHUNK (KD / BK)     // 4
#define SH_PAD 132           // padded row stride for transposed h chunk

// Precomputed small operands (allocation-free scratch)
__device__ __align__(16) float g_M[KD * ND];   // M[f][g] = sum_k W[k][f] * ng[k][g]
__device__ __align__(16) float g_b2[ND];       // b2[g]   = sum_k b[k]    * ng[k][g]
__device__ float g_fac[KD];                    // row normalization factors

// ---------------------------------------------------------------------------
// Prep kernel 1: per-row degree factor with reference clip/where semantics
// ---------------------------------------------------------------------------
__global__ void prep_fac_kernel(const float* __restrict__ graph) {
    int f = threadIdx.x;
    float rs = 0.0f;
    #pragma unroll 8
    for (int g = 0; g < ND; g++) rs += graph[f * ND + g];
    float clipped = fmaxf(rs, EPS_F);
    g_fac[f] = (clipped > EPS_F) ? (1.0f / clipped) : 0.0f;
}

// ---------------------------------------------------------------------------
// Prep kernel 2: M = W^T @ norm_graph  and  b2 = b @ norm_graph
//   grid = 128 (f), block = 128 (g). ~2 MFLOP total, negligible.
// ---------------------------------------------------------------------------
__global__ void prep_M_kernel(const float* __restrict__ graph,
                              const float* __restrict__ W,
                              const float* __restrict__ b) {
    int f = blockIdx.x;
    int g = threadIdx.x;
    float s = 0.0f;
    #pragma unroll 8
    for (int k = 0; k < KD; k++)
        s = fmaf(W[k * KD + f], graph[k * ND + g] * g_fac[k], s);
    g_M[f * ND + g] = s;
    if (f == 0) {
        float s2 = 0.0f;
        #pragma unroll 8
        for (int k = 0; k < KD; k++)
            s2 = fmaf(b[k], graph[k * ND + g] * g_fac[k], s2);
        g_b2[g] = s2;
    }
}

// ---------------------------------------------------------------------------
// Packed fp32x2 helpers (Blackwell fma.rn.f32x2: 2 FMAs per issue)
// ---------------------------------------------------------------------------
__device__ __forceinline__ unsigned long long splat2(float a) {
    unsigned long long r;
    asm("mov.b64 %0, {%1, %1};" : "=l"(r) : "r"(__float_as_uint(a)));
    return r;
}
__device__ __forceinline__ void fma2(unsigned long long& c,
                                     unsigned long long a,
                                     unsigned long long b) {
    asm("fma.rn.f32x2 %0, %1, %2, %0;" : "+l"(c) : "l"(a), "l"(b));
}

// ---------------------------------------------------------------------------
// Main fused GEMM: out[r][g] = sum_f h[r][f] * M[f][g] + b2[g]
//   CTA: 128 rows x 128 cols, 256 threads, 8x8 micro-tile per thread.
//   M fully resident in smem; h streamed in K-chunks of 32 with register
//   prefetch; accumulators packed f32x2.
// ---------------------------------------------------------------------------
__global__ void __launch_bounds__(256, 2)
fused_gemm_kernel(const float* __restrict__ h, float* __restrict__ out) {
    extern __shared__ float smem[];
    float* sM = smem;                    // [128][128] = 64 KB
    float* sh = smem + KD * ND;          // [BK][SH_PAD] transposed h chunk

    const int tid = threadIdx.x;
    const int tx = tid & 15;             // 16 col groups of 8
    const int ty = tid >> 4;             // 16 row groups of 8
    const size_t row0 = (size_t)blockIdx.x * BM;

    // Load full M into smem: 16384 floats / 256 threads = 16 float4 each.
    {
        const float4* src = (const float4*)g_M;
        float4* dst = (float4*)sM;
        #pragma unroll
        for (int i = 0; i < 16; i++) dst[tid + 256 * i] = src[tid + 256 * i];
    }

    // Prefetch h chunk 0 into registers (coalesced float4 loads).
    const float4* hg = (const float4*)(h + row0 * KD);  // row stride = 32 float4
    float4 pf[4];
    #pragma unroll
    for (int j = 0; j < 4; j++) {
        int idx = tid + 256 * j;
        int r = idx >> 3, kq = idx & 7;
        pf[j] = hg[r * 32 + kq];
    }

    // Accumulators: 8 rows x 4 f32x2 col-pairs, initialized from b2.
    unsigned long long acc[8][4];
    {
        ulonglong2 b01 = *(const ulonglong2*)(g_b2 + tx * 8);
        ulonglong2 b23 = *(const ulonglong2*)(g_b2 + tx * 8 + 4);
        #pragma unroll
        for (int r = 0; r < 8; r++) {
            acc[r][0] = b01.x; acc[r][1] = b01.y;
            acc[r][2] = b23.x; acc[r][3] = b23.y;
        }
    }

    #pragma unroll 1
    for (int c = 0; c < NCHUNK; c++) {
        // Store prefetched chunk to smem, transposed: sh[kk][row].
        #pragma unroll
        for (int j = 0; j < 4; j++) {
            int idx = tid + 256 * j;
            int r = idx >> 3, kk = (idx & 7) * 4;
            sh[(kk + 0) * SH_PAD + r] = pf[j].x;
            sh[(kk + 1) * SH_PAD + r] = pf[j].y;
            sh[(kk + 2) * SH_PAD + r] = pf[j].z;
            sh[(kk + 3) * SH_PAD + r] = pf[j].w;
        }
        __syncthreads();   // sh (and sM on first iter) ready

        // Prefetch next chunk while computing this one.
        if (c + 1 < NCHUNK) {
            #pragma unroll
            for (int j = 0; j < 4; j++) {
                int idx = tid + 256 * j;
                int r = idx >> 3, kq = idx & 7;
                pf[j] = hg[r * 32 + (c + 1) * 8 + kq];
            }
        }

        const float* sMk = sM + c * BK * ND;
        #pragma unroll 8
        for (int kk = 0; kk < BK; kk++) {
            float4 a0 = *(const float4*)(sh + kk * SH_PAD + ty * 8);
            float4 a1 = *(const float4*)(sh + kk * SH_PAD + ty * 8 + 4);
            ulonglong2 b01 = *(const ulonglong2*)(sMk + kk * ND + tx * 8);
            ulonglong2 b23 = *(const ulonglong2*)(sMk + kk * ND + tx * 8 + 4);
            float ar[8] = {a0.x, a0.y, a0.z, a0.w, a1.x, a1.y, a1.z, a1.w};
            #pragma unroll
            for (int r = 0; r < 8; r++) {
                unsigned long long a2 = splat2(ar[r]);
                fma2(acc[r][0], a2, b01.x);
                fma2(acc[r][1], a2, b01.y);
                fma2(acc[r][2], a2, b23.x);
                fma2(acc[r][3], a2, b23.y);
            }
        }
        __syncthreads();   // protect sh before next chunk's store
    }

    // Epilogue: packed accumulators have the same bit layout as float pairs.
    float* og = out + row0 * ND;
    #pragma unroll
    for (int r = 0; r < 8; r++) {
        size_t off = (size_t)(ty * 8 + r) * ND + tx * 8;
        *(ulonglong2*)(og + off)     = make_ulonglong2(acc[r][0], acc[r][1]);
        *(ulonglong2*)(og + off + 4) = make_ulonglong2(acc[r][2], acc[r][3]);
    }
}

// ---------------------------------------------------------------------------
// Launch (R2 resubmit: identical to R1 — broker-level container failure,
// no evidence against the kernel; need a clean baseline measurement)
// ---------------------------------------------------------------------------
extern "C" void kernel_launch(void* const* d_in, const int* in_sizes, int n_in,
                              void* d_out, int out_size) {
    (void)in_sizes; (void)n_in; (void)out_size;
    const float* h     = (const float*)d_in[0];
    const float* graph = (const float*)d_in[1];
    const float* W     = (const float*)d_in[2];
    const float* b     = (const float*)d_in[3];
    float* out         = (float*)d_out;

    const int smem_bytes = (KD * ND + BK * SH_PAD) * (int)sizeof(float); // ~82 KB
    cudaFuncSetAttribute(fused_gemm_kernel,
                         cudaFuncAttributeMaxDynamicSharedMemorySize, smem_bytes);

    prep_fac_kernel<<<1, KD>>>(graph);
    prep_M_kernel<<<KD, ND>>>(graph, W, b);
    fused_gemm_kernel<<<R_TOTAL / BM, 256, smem_bytes>>>(h, out);
}

// round 5
// speedup vs baseline: 1.7176x; 1.7176x over previous
#include <cuda_runtime.h>
#include <cuda_bf16.h>
#include <cstdint>

// ---------------------------------------------------------------------------
// Problem constants
// ---------------------------------------------------------------------------
#define KD      128
#define ND      128
#define R_TOTAL (32 * 8192)
#define EPS_F   1e-10f
#define NSM     148
#define NTILES  (R_TOTAL / 128)      // 2048 tiles of 128 rows

// SMEM layout (bytes). Row stride 272 = 256 data + 16 pad (bank-conflict-free
// ldmatrix, 16B-aligned rows).
#define ROWB     272
#define SB_HI    0                       // B = Mt hi  [128 x 272]
#define SB_LO    34816                   // B = Mt lo
#define SA0      69632                   // A buffers: [buf]{hi,lo}
#define SA_LO    34816                   // lo offset within a buffer
#define SA_STRIDE 69632
#define SB2      208896                  // b2, 512 B
#define MB_OFF   209408                  // mbarriers: full0 full1 free0 free1
#define SMEM_TOTAL 209472

// ---------------------------------------------------------------------------
// Precomputed small operands
// ---------------------------------------------------------------------------
__device__ __align__(16) float g_M[KD * ND];
__device__ __align__(16) float g_b2[ND];
__device__ float g_fac[KD];
__device__ __align__(16) __nv_bfloat16 g_Bhi[ND * KD];  // Mt hi: [g][f]
__device__ __align__(16) __nv_bfloat16 g_Blo[ND * KD];  // Mt lo: [g][f]

// ---------------------------------------------------------------------------
// PTX helpers
// ---------------------------------------------------------------------------
__device__ __forceinline__ uint32_t smem_u32(const void* p) {
    uint32_t a;
    asm("{ .reg .u64 t; cvta.to.shared.u64 t, %1; cvt.u32.u64 %0, t; }" : "=r"(a) : "l"(p));
    return a;
}
#define MBAR_INIT(a, n) asm volatile("mbarrier.init.shared.b64 [%0], %1;" :: "r"(a), "r"(n) : "memory")
#define MBAR_ARRIVE(a)  asm volatile("mbarrier.arrive.release.cta.shared::cta.b64 _, [%0];" :: "r"(a) : "memory")
#define MBAR_WAIT(a, ph) do {                                                     \
    uint32_t _m = (a), _p = (ph);                                                 \
    asm volatile("{\n\t.reg .pred P;\n\tWL_%=:\n\t"                               \
        "mbarrier.try_wait.parity.acquire.cta.shared::cta.b64 P, [%0], %1, 0x989680;\n\t" \
        "@P bra.uni WD_%=;\n\tbra.uni WL_%=;\n\tWD_%=:\n\t}"                      \
        :: "r"(_m), "r"(_p) : "memory");                                          \
} while (0)

#define LDSM_X4(r, a)                                                             \
    asm volatile("ldmatrix.sync.aligned.m8n8.x4.shared.b16 {%0,%1,%2,%3}, [%4];"  \
        : "=r"((r)[0]), "=r"((r)[1]), "=r"((r)[2]), "=r"((r)[3]) : "r"(a))
#define LDSM_X2(r0, r1, a)                                                        \
    asm volatile("ldmatrix.sync.aligned.m8n8.x2.shared.b16 {%0,%1}, [%2];"        \
        : "=r"(r0), "=r"(r1) : "r"(a))

__device__ __forceinline__ void mma_bf16(float* c, const uint32_t* a,
                                         uint32_t b0, uint32_t b1) {
    asm volatile(
        "mma.sync.aligned.m16n8k16.row.col.f32.bf16.bf16.f32 "
        "{%0,%1,%2,%3}, {%4,%5,%6,%7}, {%8,%9}, {%0,%1,%2,%3};"
        : "+f"(c[0]), "+f"(c[1]), "+f"(c[2]), "+f"(c[3])
        : "r"(a[0]), "r"(a[1]), "r"(a[2]), "r"(a[3]), "r"(b0), "r"(b1));
}
__device__ __forceinline__ uint32_t packbf(__nv_bfloat16 a, __nv_bfloat16 b) {
    __nv_bfloat162 t(a, b);
    return *reinterpret_cast<uint32_t*>(&t);
}

// ---------------------------------------------------------------------------
// Prep kernels
// ---------------------------------------------------------------------------
__global__ void prep_fac_kernel(const float* __restrict__ graph) {
    int f = threadIdx.x;
    float rs = 0.0f;
    #pragma unroll 8
    for (int g = 0; g < ND; g++) rs += graph[f * ND + g];
    float c = fmaxf(rs, EPS_F);
    g_fac[f] = (c > EPS_F) ? (1.0f / c) : 0.0f;
}
__global__ void prep_M_kernel(const float* __restrict__ graph,
                              const float* __restrict__ W,
                              const float* __restrict__ b) {
    int f = blockIdx.x, g = threadIdx.x;
    float s = 0.0f;
    #pragma unroll 8
    for (int k = 0; k < KD; k++)
        s = fmaf(W[k * KD + f], graph[k * ND + g] * g_fac[k], s);
    g_M[f * ND + g] = s;
    if (f == 0) {
        float s2 = 0.0f;
        #pragma unroll 8
        for (int k = 0; k < KD; k++)
            s2 = fmaf(b[k], graph[k * ND + g] * g_fac[k], s2);
        g_b2[g] = s2;
    }
}
__global__ void prep_split_kernel() {
    int g = blockIdx.x, f = threadIdx.x;
    float m = g_M[f * ND + g];
    __nv_bfloat16 hi = __float2bfloat16(m);
    g_Bhi[g * KD + f] = hi;
    g_Blo[g * KD + f] = __float2bfloat16(m - __bfloat162float(hi));
}

// ---------------------------------------------------------------------------
// Main persistent kernel: WG1 (tid 128-255) = load/split producer,
// WG0 (tid 0-127) = 4 mma.sync compute warps with register accumulators.
// ---------------------------------------------------------------------------
__global__ void __launch_bounds__(256, 1)
mp_mma_kernel(const float* __restrict__ h, float* __restrict__ out) {
    extern __shared__ char smem[];
    const uint32_t sb = smem_u32(smem);
    const int tid = threadIdx.x, wid = tid >> 5, lane = tid & 31;
    const int bid = blockIdx.x;

    // --- init: load B (Mt hi/lo) into padded smem, b2, mbarriers ---
    {
        const uint32_t* bh = (const uint32_t*)g_Bhi;
        const uint32_t* bl = (const uint32_t*)g_Blo;
        #pragma unroll 4
        for (int j = 0; j < 32; j++) {
            int w = tid + 256 * j;                  // uint32 index (2 bf16)
            int row = w >> 6, cb = (w & 63) * 4;    // byte offset in row
            *(uint32_t*)(smem + SB_HI + row * ROWB + cb) = bh[w];
            *(uint32_t*)(smem + SB_LO + row * ROWB + cb) = bl[w];
        }
        if (tid < ND) *(float*)(smem + SB2 + tid * 4) = g_b2[tid];
        if (tid == 0) {
            MBAR_INIT(sb + MB_OFF + 0, 128);   // full[0]  (producer arrives)
            MBAR_INIT(sb + MB_OFF + 8, 128);   // full[1]
            MBAR_INIT(sb + MB_OFF + 16, 128);  // free[0]  (consumers arrive)
            MBAR_INIT(sb + MB_OFF + 24, 128);  // free[1]
        }
    }
    __syncthreads();

    const int nt = (NTILES - bid + NSM - 1) / NSM;   // 13 or 14 tiles

    if (tid >= 128) {
        // ================= producer warpgroup =================
        const int wt = tid - 128;
        for (int it = 0; it < nt; ++it) {
            const int p = it & 1, ph = (it >> 1) & 1;
            if (it >= 2) MBAR_WAIT(sb + MB_OFF + 16 + 8 * p, ph ^ 1);
            const float4* hg = (const float4*)h + (size_t)(bid + it * NSM) * 4096;
            char* aHi = smem + SA0 + p * SA_STRIDE;
            char* aLo = aHi + SA_LO;
            #pragma unroll 4
            for (int j = 0; j < 32; j++) {
                int v = wt + 128 * j;
                float4 x = hg[v];
                int row = v >> 5, cb = (v & 31) * 8;   // byte offset (4 bf16)
                __nv_bfloat16 h0 = __float2bfloat16(x.x);
                __nv_bfloat16 h1 = __float2bfloat16(x.y);
                __nv_bfloat16 h2 = __float2bfloat16(x.z);
                __nv_bfloat16 h3 = __float2bfloat16(x.w);
                __nv_bfloat16 l0 = __float2bfloat16(x.x - __bfloat162float(h0));
                __nv_bfloat16 l1 = __float2bfloat16(x.y - __bfloat162float(h1));
                __nv_bfloat16 l2 = __float2bfloat16(x.z - __bfloat162float(h2));
                __nv_bfloat16 l3 = __float2bfloat16(x.w - __bfloat162float(h3));
                *(uint2*)(aHi + row * ROWB + cb) = make_uint2(packbf(h0, h1), packbf(h2, h3));
                *(uint2*)(aLo + row * ROWB + cb) = make_uint2(packbf(l0, l1), packbf(l2, l3));
            }
            MBAR_ARRIVE(sb + MB_OFF + 8 * p);
        }
    } else {
        // ================= compute warpgroup =================
        // ldmatrix per-lane offsets.
        const int lm = lane >> 3, lr = lane & 7;
        const uint32_t aOff = (uint32_t)(((lm & 1) * 8 + lr) * ROWB + (lm >> 1) * 16);
        const uint32_t bOff = (uint32_t)(lr * ROWB + (lm & 1) * 16);
        const uint32_t bHiBase = sb + SB_HI + bOff;
        const uint32_t bLoBase = sb + SB_LO + bOff;

        for (int it = 0; it < nt; ++it) {
            const int p = it & 1, ph = (it >> 1) & 1;
            MBAR_WAIT(sb + MB_OFF + 8 * p, ph);

            const uint32_t aHiB = sb + SA0 + p * SA_STRIDE + wid * 32 * ROWB + aOff;
            const uint32_t aLoB = aHiB + SA_LO;

            float acc[2][16][4];
            #pragma unroll
            for (int mt = 0; mt < 2; mt++)
                #pragma unroll
                for (int n = 0; n < 16; n++)
                    #pragma unroll
                    for (int q = 0; q < 4; q++) acc[mt][n][q] = 0.0f;

            #pragma unroll 1
            for (int ks = 0; ks < 8; ks++) {
                const uint32_t koff = ks * 32;      // 16 bf16 = 32 B
                uint32_t ah0[4], ah1[4], al0[4], al1[4];
                LDSM_X4(ah0, aHiB + koff);
                LDSM_X4(ah1, aHiB + 16 * ROWB + koff);
                LDSM_X4(al0, aLoB + koff);
                LDSM_X4(al1, aLoB + 16 * ROWB + koff);
                #pragma unroll
                for (int n = 0; n < 16; n++) {
                    uint32_t bh0, bh1, bl0, bl1;
                    LDSM_X2(bh0, bh1, bHiBase + n * 8 * ROWB + koff);
                    LDSM_X2(bl0, bl1, bLoBase + n * 8 * ROWB + koff);
                    mma_bf16(acc[0][n], ah0, bh0, bh1);
                    mma_bf16(acc[1][n], ah1, bh0, bh1);
                    mma_bf16(acc[0][n], al0, bh0, bh1);
                    mma_bf16(acc[1][n], al1, bh0, bh1);
                    mma_bf16(acc[0][n], ah0, bl0, bl1);
                    mma_bf16(acc[1][n], ah1, bl0, bl1);
                }
            }
            MBAR_ARRIVE(sb + MB_OFF + 16 + 8 * p);   // buffer free (results in regs)

            // epilogue: + b2, direct STG
            float2 bb[16];
            #pragma unroll
            for (int n = 0; n < 16; n++)
                bb[n] = *(const float2*)(smem + SB2 + (n * 8 + (lane & 3) * 2) * 4);
            const size_t tile = (size_t)(bid + it * NSM);
            #pragma unroll
            for (int mt = 0; mt < 2; mt++) {
                size_t r0 = tile * 128 + wid * 32 + mt * 16 + (lane >> 2);
                float* o = out + r0 * ND + (lane & 3) * 2;
                #pragma unroll
                for (int n = 0; n < 16; n++) {
                    *(float2*)(o + n * 8) =
                        make_float2(acc[mt][n][0] + bb[n].x, acc[mt][n][1] + bb[n].y);
                    *(float2*)(o + 8 * ND + n * 8) =
                        make_float2(acc[mt][n][2] + bb[n].x, acc[mt][n][3] + bb[n].y);
                }
            }
        }
    }
}

// ---------------------------------------------------------------------------
// Launch
// ---------------------------------------------------------------------------
extern "C" void kernel_launch(void* const* d_in, const int* in_sizes, int n_in,
                              void* d_out, int out_size) {
    (void)in_sizes; (void)n_in; (void)out_size;
    const float* h     = (const float*)d_in[0];
    const float* graph = (const float*)d_in[1];
    const float* W     = (const float*)d_in[2];
    const float* b     = (const float*)d_in[3];
    float* out         = (float*)d_out;

    cudaFuncSetAttribute(mp_mma_kernel,
                         cudaFuncAttributeMaxDynamicSharedMemorySize, SMEM_TOTAL);

    prep_fac_kernel<<<1, KD>>>(graph);
    prep_M_kernel<<<KD, ND>>>(graph, W, b);
    prep_split_kernel<<<ND, KD>>>();
    mp_mma_kernel<<<NSM, 256, SMEM_TOTAL>>>(h, out);
}

// round 6
// speedup vs baseline: 1.9087x; 1.1112x over previous
#include <cuda_runtime.h>
#include <cuda_bf16.h>
#include <cstdint>

// ---------------------------------------------------------------------------
// Problem constants
// ---------------------------------------------------------------------------
#define KD      128
#define ND      128
#define R_TOTAL (32 * 8192)
#define EPS_F   1e-10f
#define NSM     148
#define NTILES  (R_TOTAL / 128)      // 2048 tiles of 128 rows

// SMEM layout (bytes). Row stride 272 = 256 data + 16 pad.
#define ROWB     272
#define SB_HI    0                       // B = Mt hi  [128 x 272]
#define SB_LO    34816                   // B = Mt lo
#define SA0      69632                   // A buffers: [buf]{hi,lo}
#define SA_LO    34816
#define SA_STRIDE 69632
#define SB2      208896                  // b2, 512 B
#define MB_OFF   209408                  // mbarriers: full0 full1 free0 free1
#define SMEM_TOTAL 209472

#define NTHREADS 384                     // 8 compute warps + 4 producer warps

// ---------------------------------------------------------------------------
// Precomputed small operands
// ---------------------------------------------------------------------------
__device__ __align__(16) float g_b2[ND];
__device__ float g_fac[KD];
__device__ __align__(16) __nv_bfloat16 g_Bhi[ND * KD];  // Mt hi: [g][f]
__device__ __align__(16) __nv_bfloat16 g_Blo[ND * KD];  // Mt lo: [g][f]

// ---------------------------------------------------------------------------
// PTX helpers
// ---------------------------------------------------------------------------
__device__ __forceinline__ uint32_t smem_u32(const void* p) {
    uint32_t a;
    asm("{ .reg .u64 t; cvta.to.shared.u64 t, %1; cvt.u32.u64 %0, t; }" : "=r"(a) : "l"(p));
    return a;
}
#define MBAR_INIT(a, n) asm volatile("mbarrier.init.shared.b64 [%0], %1;" :: "r"(a), "r"(n) : "memory")
#define MBAR_ARRIVE(a)  asm volatile("mbarrier.arrive.release.cta.shared::cta.b64 _, [%0];" :: "r"(a) : "memory")
#define MBAR_WAIT(a, ph) do {                                                     \
    uint32_t _m = (a), _p = (ph);                                                 \
    asm volatile("{\n\t.reg .pred P;\n\tWL_%=:\n\t"                               \
        "mbarrier.try_wait.parity.acquire.cta.shared::cta.b64 P, [%0], %1, 0x989680;\n\t" \
        "@P bra.uni WD_%=;\n\tbra.uni WL_%=;\n\tWD_%=:\n\t}"                      \
        :: "r"(_m), "r"(_p) : "memory");                                          \
} while (0)

#define LDSM_X4(r, a)                                                             \
    asm volatile("ldmatrix.sync.aligned.m8n8.x4.shared.b16 {%0,%1,%2,%3}, [%4];"  \
        : "=r"((r)[0]), "=r"((r)[1]), "=r"((r)[2]), "=r"((r)[3]) : "r"(a))
#define LDSM_X2(r0, r1, a)                                                        \
    asm volatile("ldmatrix.sync.aligned.m8n8.x2.shared.b16 {%0,%1}, [%2];"        \
        : "=r"(r0), "=r"(r1) : "r"(a))

__device__ __forceinline__ void mma_bf16(float* c, const uint32_t* a,
                                         uint32_t b0, uint32_t b1) {
    asm volatile(
        "mma.sync.aligned.m16n8k16.row.col.f32.bf16.bf16.f32 "
        "{%0,%1,%2,%3}, {%4,%5,%6,%7}, {%8,%9}, {%0,%1,%2,%3};"
        : "+f"(c[0]), "+f"(c[1]), "+f"(c[2]), "+f"(c[3])
        : "r"(a[0]), "r"(a[1]), "r"(a[2]), "r"(a[3]), "r"(b0), "r"(b1));
}
__device__ __forceinline__ uint32_t packbf(__nv_bfloat16 a, __nv_bfloat16 b) {
    __nv_bfloat162 t(a, b);
    return *reinterpret_cast<uint32_t*>(&t);
}

// ---------------------------------------------------------------------------
// Prep kernel 1: fac[f] = safe 1/rowsum. 128 blocks x 1 warp, shfl reduce.
// ---------------------------------------------------------------------------
__global__ void prep_fac_kernel(const float* __restrict__ graph) {
    int f = blockIdx.x, lane = threadIdx.x;
    float s = 0.0f;
    #pragma unroll
    for (int j = 0; j < 4; j++) s += graph[f * ND + lane + 32 * j];
    #pragma unroll
    for (int o = 16; o > 0; o >>= 1) s += __shfl_xor_sync(0xFFFFFFFFu, s, o);
    if (lane == 0) {
        float c = fmaxf(s, EPS_F);
        g_fac[f] = (c > EPS_F) ? (1.0f / c) : 0.0f;
    }
}

// ---------------------------------------------------------------------------
// Prep kernel 2 (fused): blocks 0-127 compute M row f and write bf16 hi/lo
// split directly (Mt layout [g][f]); block 128 computes b2.
// W[k][f] loads are warp-broadcast, graph[k][g] coalesced, all L2-hot.
// ---------------------------------------------------------------------------
__global__ void prep_Msplit_kernel(const float* __restrict__ graph,
                                   const float* __restrict__ W,
                                   const float* __restrict__ b) {
    int g = threadIdx.x;
    if (blockIdx.x < KD) {
        int f = blockIdx.x;
        float s = 0.0f;
        #pragma unroll 8
        for (int k = 0; k < KD; k++)
            s = fmaf(W[k * KD + f], graph[k * ND + g] * g_fac[k], s);
        __nv_bfloat16 hi = __float2bfloat16(s);
        g_Bhi[g * KD + f] = hi;
        g_Blo[g * KD + f] = __float2bfloat16(s - __bfloat162float(hi));
    } else {
        float s2 = 0.0f;
        #pragma unroll 8
        for (int k = 0; k < KD; k++)
            s2 = fmaf(b[k], graph[k * ND + g] * g_fac[k], s2);
        g_b2[g] = s2;
    }
}

// ---------------------------------------------------------------------------
// Main persistent kernel.
//   Warps 0-7 : compute; 2D partition, warp w owns rows (w>>1)*32..+32,
//               cols (w&1)*64..+64 of the 128x128 tile. 2 MMA warps/SMSP.
//   Warps 8-11: producer; load h fp32 -> bf16 hi/lo split -> smem.
// ---------------------------------------------------------------------------
__global__ void __launch_bounds__(NTHREADS, 1)
mp_mma_kernel(const float* __restrict__ h, float* __restrict__ out) {
    extern __shared__ char smem[];
    const uint32_t sb = smem_u32(smem);
    const int tid = threadIdx.x, wid = tid >> 5, lane = tid & 31;
    const int bid = blockIdx.x;

    // --- init: B (Mt hi/lo) into padded smem, b2, mbarriers ---
    {
        const uint32_t* bh = (const uint32_t*)g_Bhi;
        const uint32_t* bl = (const uint32_t*)g_Blo;
        for (int w = tid; w < 8192; w += NTHREADS) {     // uint32 index (2 bf16)
            int row = w >> 6, cb = (w & 63) * 4;
            *(uint32_t*)(smem + SB_HI + row * ROWB + cb) = bh[w];
            *(uint32_t*)(smem + SB_LO + row * ROWB + cb) = bl[w];
        }
        if (tid < ND) *(float*)(smem + SB2 + tid * 4) = g_b2[tid];
        if (tid == 0) {
            MBAR_INIT(sb + MB_OFF + 0, 128);   // full[0]  (128 producer threads)
            MBAR_INIT(sb + MB_OFF + 8, 128);   // full[1]
            MBAR_INIT(sb + MB_OFF + 16, 256);  // free[0]  (256 consumer threads)
            MBAR_INIT(sb + MB_OFF + 24, 256);  // free[1]
        }
    }
    __syncthreads();

    const int nt = (NTILES - bid + NSM - 1) / NSM;   // 13 or 14 tiles

    if (wid >= 8) {
        // ================= producer warpgroup (4 warps) =================
        const int wt = tid - 256;
        for (int it = 0; it < nt; ++it) {
            const int p = it & 1, ph = (it >> 1) & 1;
            if (it >= 2) MBAR_WAIT(sb + MB_OFF + 16 + 8 * p, ph ^ 1);
            const float4* hg = (const float4*)h + (size_t)(bid + it * NSM) * 4096;
            char* aHi = smem + SA0 + p * SA_STRIDE;
            char* aLo = aHi + SA_LO;
            #pragma unroll 4
            for (int j = 0; j < 32; j++) {
                int v = wt + 128 * j;
                float4 x = hg[v];
                int row = v >> 5, cb = (v & 31) * 8;
                __nv_bfloat16 h0 = __float2bfloat16(x.x);
                __nv_bfloat16 h1 = __float2bfloat16(x.y);
                __nv_bfloat16 h2 = __float2bfloat16(x.z);
                __nv_bfloat16 h3 = __float2bfloat16(x.w);
                __nv_bfloat16 l0 = __float2bfloat16(x.x - __bfloat162float(h0));
                __nv_bfloat16 l1 = __float2bfloat16(x.y - __bfloat162float(h1));
                __nv_bfloat16 l2 = __float2bfloat16(x.z - __bfloat162float(h2));
                __nv_bfloat16 l3 = __float2bfloat16(x.w - __bfloat162float(h3));
                *(uint2*)(aHi + row * ROWB + cb) = make_uint2(packbf(h0, h1), packbf(h2, h3));
                *(uint2*)(aLo + row * ROWB + cb) = make_uint2(packbf(l0, l1), packbf(l2, l3));
            }
            MBAR_ARRIVE(sb + MB_OFF + 8 * p);
        }
    } else {
        // ================= compute warps (8) =================
        const int mrow = (wid >> 1) * 32;            // row quadrant base
        const int ncol = (wid & 1) * 64;             // col quadrant base
        const int lm = lane >> 3, lr = lane & 7;
        const uint32_t aOff = (uint32_t)(((lm & 1) * 8 + lr) * ROWB + (lm >> 1) * 16);
        const uint32_t bOff = (uint32_t)(lr * ROWB + (lm & 1) * 16);
        const uint32_t bHiBase = sb + SB_HI + ncol * ROWB + bOff;
        const uint32_t bLoBase = sb + SB_LO + ncol * ROWB + bOff;

        for (int it = 0; it < nt; ++it) {
            const int p = it & 1, ph = (it >> 1) & 1;
            MBAR_WAIT(sb + MB_OFF + 8 * p, ph);

            const uint32_t aB = sb + SA0 + p * SA_STRIDE + mrow * ROWB + aOff;

            float acc[2][8][4];
            #pragma unroll
            for (int mt = 0; mt < 2; mt++)
                #pragma unroll
                for (int n = 0; n < 8; n++)
                    #pragma unroll
                    for (int q = 0; q < 4; q++) acc[mt][n][q] = 0.0f;

            #pragma unroll 1
            for (int ks = 0; ks < 8; ks++) {
                const uint32_t koff = ks * 32;       // 16 bf16 = 32 B
                uint32_t ah[2][4], al[2][4];
                LDSM_X4(ah[0], aB + koff);
                LDSM_X4(ah[1], aB + 16 * ROWB + koff);
                LDSM_X4(al[0], aB + SA_LO + koff);
                LDSM_X4(al[1], aB + SA_LO + 16 * ROWB + koff);
                #pragma unroll
                for (int n = 0; n < 8; n++) {
                    uint32_t bh0, bh1, bl0, bl1;
                    LDSM_X2(bh0, bh1, bHiBase + n * 8 * ROWB + koff);
                    LDSM_X2(bl0, bl1, bLoBase + n * 8 * ROWB + koff);
                    mma_bf16(acc[0][n], ah[0], bh0, bh1);
                    mma_bf16(acc[1][n], ah[1], bh0, bh1);
                    mma_bf16(acc[0][n], al[0], bh0, bh1);
                    mma_bf16(acc[1][n], al[1], bh0, bh1);
                    mma_bf16(acc[0][n], ah[0], bl0, bl1);
                    mma_bf16(acc[1][n], ah[1], bl0, bl1);
                }
            }
            MBAR_ARRIVE(sb + MB_OFF + 16 + 8 * p);   // buffer free (results in regs)

            // epilogue: + b2, direct STG
            float2 bb[8];
            #pragma unroll
            for (int n = 0; n < 8; n++)
                bb[n] = *(const float2*)(smem + SB2 + (ncol + n * 8 + (lane & 3) * 2) * 4);
            const size_t tile = (size_t)(bid + it * NSM);
            #pragma unroll
            for (int mt = 0; mt < 2; mt++) {
                size_t r0 = tile * 128 + mrow + mt * 16 + (lane >> 2);
                float* o = out + r0 * ND + ncol + (lane & 3) * 2;
                #pragma unroll
                for (int n = 0; n < 8; n++) {
                    *(float2*)(o + n * 8) =
                        make_float2(acc[mt][n][0] + bb[n].x, acc[mt][n][1] + bb[n].y);
                    *(float2*)(o + 8 * ND + n * 8) =
                        make_float2(acc[mt][n][2] + bb[n].x, acc[mt][n][3] + bb[n].y);
                }
            }
        }
    }
}

// ---------------------------------------------------------------------------
// Launch
// ---------------------------------------------------------------------------
extern "C" void kernel_launch(void* const* d_in, const int* in_sizes, int n_in,
                              void* d_out, int out_size) {
    (void)in_sizes; (void)n_in; (void)out_size;
    const float* h     = (const float*)d_in[0];
    const float* graph = (const float*)d_in[1];
    const float* W     = (const float*)d_in[2];
    const float* b     = (const float*)d_in[3];
    float* out         = (float*)d_out;

    cudaFuncSetAttribute(mp_mma_kernel,
                         cudaFuncAttributeMaxDynamicSharedMemorySize, SMEM_TOTAL);

    prep_fac_kernel<<<KD, 32>>>(graph);
    prep_Msplit_kernel<<<KD + 1, ND>>>(graph, W, b);
    mp_mma_kernel<<<NSM, NTHREADS, SMEM_TOTAL>>>(h, out);
}

// round 7
// speedup vs baseline: 2.0661x; 1.0825x over previous
#include <cuda_runtime.h>
#include <cuda_fp16.h>
#include <cstdint>

// ---------------------------------------------------------------------------
// Problem constants
// ---------------------------------------------------------------------------
#define KD      128
#define ND      128
#define R_TOTAL (32 * 8192)
#define EPS_F   1e-10f
#define NSM     148
#define NTILES  (R_TOTAL / 128)      // 2048 tiles of 128 rows

// SMEM layout (bytes). Row stride 272 = 256 data + 16 pad.
#define ROWB     272
#define SB_HI    0                       // B = Mt hi (fp16) [128 x 272]
#define SB_LO    34816                   // B = Mt lo (fp16 correction)
#define SA0      69632                   // A buffers (fp16, single part)
#define SA_STRIDE 34816
#define SB2      139264                  // b2, 512 B
#define MB_OFF   139776                  // mbarriers: full0 full1 free0 free1
#define SMEM_TOTAL 139840

#define NTHREADS 384                     // 8 compute warps + 4 producer warps

// ---------------------------------------------------------------------------
// Precomputed small operands
// ---------------------------------------------------------------------------
__device__ __align__(16) float g_b2[ND];
__device__ float g_fac[KD];
__device__ __align__(16) __half g_Bhi[ND * KD];  // Mt hi: [g][f]
__device__ __align__(16) __half g_Blo[ND * KD];  // Mt lo: [g][f]

// ---------------------------------------------------------------------------
// PTX helpers
// ---------------------------------------------------------------------------
__device__ __forceinline__ uint32_t smem_u32(const void* p) {
    uint32_t a;
    asm("{ .reg .u64 t; cvta.to.shared.u64 t, %1; cvt.u32.u64 %0, t; }" : "=r"(a) : "l"(p));
    return a;
}
#define MBAR_INIT(a, n) asm volatile("mbarrier.init.shared.b64 [%0], %1;" :: "r"(a), "r"(n) : "memory")
#define MBAR_ARRIVE(a)  asm volatile("mbarrier.arrive.release.cta.shared::cta.b64 _, [%0];" :: "r"(a) : "memory")
#define MBAR_WAIT(a, ph) do {                                                     \
    uint32_t _m = (a), _p = (ph);                                                 \
    asm volatile("{\n\t.reg .pred P;\n\tWL_%=:\n\t"                               \
        "mbarrier.try_wait.parity.acquire.cta.shared::cta.b64 P, [%0], %1, 0x989680;\n\t" \
        "@P bra.uni WD_%=;\n\tbra.uni WL_%=;\n\tWD_%=:\n\t}"                      \
        :: "r"(_m), "r"(_p) : "memory");                                          \
} while (0)

#define LDSM_X4(r, a)                                                             \
    asm volatile("ldmatrix.sync.aligned.m8n8.x4.shared.b16 {%0,%1,%2,%3}, [%4];"  \
        : "=r"((r)[0]), "=r"((r)[1]), "=r"((r)[2]), "=r"((r)[3]) : "r"(a))
#define LDSM_X2(r0, r1, a)                                                        \
    asm volatile("ldmatrix.sync.aligned.m8n8.x2.shared.b16 {%0,%1}, [%2];"        \
        : "=r"(r0), "=r"(r1) : "r"(a))

__device__ __forceinline__ void mma_f16(float* c, const uint32_t* a,
                                        uint32_t b0, uint32_t b1) {
    asm volatile(
        "mma.sync.aligned.m16n8k16.row.col.f32.f16.f16.f32 "
        "{%0,%1,%2,%3}, {%4,%5,%6,%7}, {%8,%9}, {%0,%1,%2,%3};"
        : "+f"(c[0]), "+f"(c[1]), "+f"(c[2]), "+f"(c[3])
        : "r"(a[0]), "r"(a[1]), "r"(a[2]), "r"(a[3]), "r"(b0), "r"(b1));
}

// ---------------------------------------------------------------------------
// Prep kernel 1: fac[f] = safe 1/rowsum. 128 blocks x 1 warp, shfl reduce.
// ---------------------------------------------------------------------------
__global__ void prep_fac_kernel(const float* __restrict__ graph) {
    int f = blockIdx.x, lane = threadIdx.x;
    float s = 0.0f;
    #pragma unroll
    for (int j = 0; j < 4; j++) s += graph[f * ND + lane + 32 * j];
    #pragma unroll
    for (int o = 16; o > 0; o >>= 1) s += __shfl_xor_sync(0xFFFFFFFFu, s, o);
    if (lane == 0) {
        float c = fmaxf(s, EPS_F);
        g_fac[f] = (c > EPS_F) ? (1.0f / c) : 0.0f;
    }
}

// ---------------------------------------------------------------------------
// Prep kernel 2 (fused): blocks 0-127 compute M row f and write fp16 hi/lo
// split directly (Mt layout [g][f]); block 128 computes b2.
// ---------------------------------------------------------------------------
__global__ void prep_Msplit_kernel(const float* __restrict__ graph,
                                   const float* __restrict__ W,
                                   const float* __restrict__ b) {
    int g = threadIdx.x;
    if (blockIdx.x < KD) {
        int f = blockIdx.x;
        float s = 0.0f;
        #pragma unroll 8
        for (int k = 0; k < KD; k++)
            s = fmaf(W[k * KD + f], graph[k * ND + g] * g_fac[k], s);
        __half hi = __float2half(s);
        g_Bhi[g * KD + f] = hi;
        g_Blo[g * KD + f] = __float2half(s - __half2float(hi));
    } else {
        float s2 = 0.0f;
        #pragma unroll 8
        for (int k = 0; k < KD; k++)
            s2 = fmaf(b[k], graph[k * ND + g] * g_fac[k], s2);
        g_b2[g] = s2;
    }
}

// ---------------------------------------------------------------------------
// Main persistent kernel.
//   Warps 0-7 : compute; warp w owns rows (w>>1)*32..+32, cols (w&1)*64..+64.
//               2 MMA warps/SMSP. A fp16 single; B fp16 hi + lo (2 passes).
//   Warps 8-11: producer; load h fp32 -> fp16 -> smem.
// ---------------------------------------------------------------------------
__global__ void __launch_bounds__(NTHREADS, 1)
mp_mma_kernel(const float* __restrict__ h, float* __restrict__ out) {
    extern __shared__ char smem[];
    const uint32_t sb = smem_u32(smem);
    const int tid = threadIdx.x, wid = tid >> 5, lane = tid & 31;
    const int bid = blockIdx.x;

    // --- init: B (Mt hi/lo) into padded smem, b2, mbarriers ---
    {
        const uint32_t* bh = (const uint32_t*)g_Bhi;
        const uint32_t* bl = (const uint32_t*)g_Blo;
        for (int w = tid; w < 8192; w += NTHREADS) {     // uint32 index (2 fp16)
            int row = w >> 6, cb = (w & 63) * 4;
            *(uint32_t*)(smem + SB_HI + row * ROWB + cb) = bh[w];
            *(uint32_t*)(smem + SB_LO + row * ROWB + cb) = bl[w];
        }
        if (tid < ND) *(float*)(smem + SB2 + tid * 4) = g_b2[tid];
        if (tid == 0) {
            MBAR_INIT(sb + MB_OFF + 0, 128);   // full[0]  (128 producer threads)
            MBAR_INIT(sb + MB_OFF + 8, 128);   // full[1]
            MBAR_INIT(sb + MB_OFF + 16, 256);  // free[0]  (256 consumer threads)
            MBAR_INIT(sb + MB_OFF + 24, 256);  // free[1]
        }
    }
    __syncthreads();

    const int nt = (NTILES - bid + NSM - 1) / NSM;   // 13 or 14 tiles

    if (wid >= 8) {
        // ================= producer warpgroup (4 warps) =================
        const int wt = tid - 256;
        for (int it = 0; it < nt; ++it) {
            const int p = it & 1, ph = (it >> 1) & 1;
            if (it >= 2) MBAR_WAIT(sb + MB_OFF + 16 + 8 * p, ph ^ 1);
            const float4* hg = (const float4*)h + (size_t)(bid + it * NSM) * 4096;
            char* aB = smem + SA0 + p * SA_STRIDE;
            #pragma unroll 4
            for (int j = 0; j < 32; j++) {
                int v = wt + 128 * j;
                float4 x = hg[v];
                int row = v >> 5, cb = (v & 31) * 8;     // 4 fp16 = 8 bytes
                __half2 p01 = __floats2half2_rn(x.x, x.y);
                __half2 p23 = __floats2half2_rn(x.z, x.w);
                *(uint2*)(aB + row * ROWB + cb) =
                    make_uint2(*(uint32_t*)&p01, *(uint32_t*)&p23);
            }
            MBAR_ARRIVE(sb + MB_OFF + 8 * p);
        }
    } else {
        // ================= compute warps (8) =================
        const int mrow = (wid >> 1) * 32;            // row quadrant base
        const int ncol = (wid & 1) * 64;             // col quadrant base
        const int lm = lane >> 3, lr = lane & 7;
        const uint32_t aOff = (uint32_t)(((lm & 1) * 8 + lr) * ROWB + (lm >> 1) * 16);
        const uint32_t bOff = (uint32_t)(lr * ROWB + (lm & 1) * 16);
        const uint32_t bHiBase = sb + SB_HI + ncol * ROWB + bOff;
        const uint32_t bLoBase = sb + SB_LO + ncol * ROWB + bOff;

        for (int it = 0; it < nt; ++it) {
            const int p = it & 1, ph = (it >> 1) & 1;
            MBAR_WAIT(sb + MB_OFF + 8 * p, ph);

            const uint32_t aB = sb + SA0 + p * SA_STRIDE + mrow * ROWB + aOff;

            float acc[2][8][4];
            #pragma unroll
            for (int mt = 0; mt < 2; mt++)
                #pragma unroll
                for (int n = 0; n < 8; n++)
                    #pragma unroll
                    for (int q = 0; q < 4; q++) acc[mt][n][q] = 0.0f;

            #pragma unroll 1
            for (int ks = 0; ks < 8; ks++) {
                const uint32_t koff = ks * 32;       // 16 fp16 = 32 B
                uint32_t a0[4], a1[4];
                LDSM_X4(a0, aB + koff);
                LDSM_X4(a1, aB + 16 * ROWB + koff);
                #pragma unroll
                for (int n = 0; n < 8; n++) {
                    uint32_t bh0, bh1, bl0, bl1;
                    LDSM_X2(bh0, bh1, bHiBase + n * 8 * ROWB + koff);
                    LDSM_X2(bl0, bl1, bLoBase + n * 8 * ROWB + koff);
                    mma_f16(acc[0][n], a0, bh0, bh1);
                    mma_f16(acc[1][n], a1, bh0, bh1);
                    mma_f16(acc[0][n], a0, bl0, bl1);
                    mma_f16(acc[1][n], a1, bl0, bl1);
                }
            }
            MBAR_ARRIVE(sb + MB_OFF + 16 + 8 * p);   // buffer free (results in regs)

            // epilogue: + b2, direct STG
            float2 bb[8];
            #pragma unroll
            for (int n = 0; n < 8; n++)
                bb[n] = *(const float2*)(smem + SB2 + (ncol + n * 8 + (lane & 3) * 2) * 4);
            const size_t tile = (size_t)(bid + it * NSM);
            #pragma unroll
            for (int mt = 0; mt < 2; mt++) {
                size_t r0 = tile * 128 + mrow + mt * 16 + (lane >> 2);
                float* o = out + r0 * ND + ncol + (lane & 3) * 2;
                #pragma unroll
                for (int n = 0; n < 8; n++) {
                    *(float2*)(o + n * 8) =
                        make_float2(acc[mt][n][0] + bb[n].x, acc[mt][n][1] + bb[n].y);
                    *(float2*)(o + 8 * ND + n * 8) =
                        make_float2(acc[mt][n][2] + bb[n].x, acc[mt][n][3] + bb[n].y);
                }
            }
        }
    }
}

// ---------------------------------------------------------------------------
// Launch
// ---------------------------------------------------------------------------
extern "C" void kernel_launch(void* const* d_in, const int* in_sizes, int n_in,
                              void* d_out, int out_size) {
    (void)in_sizes; (void)n_in; (void)out_size;
    const float* h     = (const float*)d_in[0];
    const float* graph = (const float*)d_in[1];
    const float* W     = (const float*)d_in[2];
    const float* b     = (const float*)d_in[3];
    float* out         = (float*)d_out;

    cudaFuncSetAttribute(mp_mma_kernel,
                         cudaFuncAttributeMaxDynamicSharedMemorySize, SMEM_TOTAL);

    prep_fac_kernel<<<KD, 32>>>(graph);
    prep_Msplit_kernel<<<KD + 1, ND>>>(graph, W, b);
    mp_mma_kernel<<<NSM, NTHREADS, SMEM_TOTAL>>>(h, out);
}

// round 9
// speedup vs baseline: 3.1397x; 1.5197x over previous
#include <cuda_runtime.h>
#include <cuda_fp16.h>
#include <cstdint>

// ---------------------------------------------------------------------------
// Problem constants
// ---------------------------------------------------------------------------
#define KD      128
#define ND      128
#define R_TOTAL (32 * 8192)
#define EPS_F   1e-10f
#define NSM     148
#define NTILES  (R_TOTAL / 128)      // 2048 tiles of 128 rows

// SMEM layout (bytes). Row stride 272 = 256 data + 16 pad.
#define ROWB     272
#define SB_HI    0                       // B = Mt hi (fp16) [128 x 272]
#define SB_LO    34816                   // B = Mt lo (fp16 correction)
#define SA0      69632                   // A buffers (fp16, single part)
#define SA_STRIDE 34816
#define SB2      139264                  // b2, 512 B
#define MB_OFF   139776                  // mbarriers: full0 full1 free0 free1
#define SMEM_TOTAL 139840

#define NTHREADS 384                     // 8 compute warps + 4 producer warps

// ---------------------------------------------------------------------------
// Precomputed small operands
// ---------------------------------------------------------------------------
__device__ __align__(16) float g_b2[ND];
__device__ float g_fac[KD];
__device__ __align__(16) __half g_Bhi[ND * KD];  // Mt hi: [g][f]
__device__ __align__(16) __half g_Blo[ND * KD];  // Mt lo: [g][f]

// ---------------------------------------------------------------------------
// PTX helpers
// ---------------------------------------------------------------------------
__device__ __forceinline__ uint32_t smem_u32(const void* p) {
    uint32_t a;
    asm("{ .reg .u64 t; cvta.to.shared.u64 t, %1; cvt.u32.u64 %0, t; }" : "=r"(a) : "l"(p));
    return a;
}
#define MBAR_INIT(a, n) asm volatile("mbarrier.init.shared.b64 [%0], %1;" :: "r"(a), "r"(n) : "memory")
#define MBAR_ARRIVE(a)  asm volatile("mbarrier.arrive.release.cta.shared::cta.b64 _, [%0];" :: "r"(a) : "memory")
#define MBAR_WAIT(a, ph) do {                                                     \
    uint32_t _m = (a), _p = (ph);                                                 \
    asm volatile("{\n\t.reg .pred P;\n\tWL_%=:\n\t"                               \
        "mbarrier.try_wait.parity.acquire.cta.shared::cta.b64 P, [%0], %1, 0x989680;\n\t" \
        "@P bra.uni WD_%=;\n\tbra.uni WL_%=;\n\tWD_%=:\n\t}"                      \
        :: "r"(_m), "r"(_p) : "memory");                                          \
} while (0)

#define LDSM_X4(r, a)                                                             \
    asm volatile("ldmatrix.sync.aligned.m8n8.x4.shared.b16 {%0,%1,%2,%3}, [%4];"  \
        : "=r"((r)[0]), "=r"((r)[1]), "=r"((r)[2]), "=r"((r)[3]) : "r"(a))

__device__ __forceinline__ void mma_f16(float* c, const uint32_t* a,
                                        uint32_t b0, uint32_t b1) {
    asm volatile(
        "mma.sync.aligned.m16n8k16.row.col.f32.f16.f16.f32 "
        "{%0,%1,%2,%3}, {%4,%5,%6,%7}, {%8,%9}, {%0,%1,%2,%3};"
        : "+f"(c[0]), "+f"(c[1]), "+f"(c[2]), "+f"(c[3])
        : "r"(a[0]), "r"(a[1]), "r"(a[2]), "r"(a[3]), "r"(b0), "r"(b1));
}

// ---------------------------------------------------------------------------
// Prep kernel 1: fac[f] = safe 1/rowsum. 128 blocks x 1 warp, shfl reduce.
// ---------------------------------------------------------------------------
__global__ void prep_fac_kernel(const float* __restrict__ graph) {
    int f = blockIdx.x, lane = threadIdx.x;
    float s = 0.0f;
    #pragma unroll
    for (int j = 0; j < 4; j++) s += graph[f * ND + lane + 32 * j];
    #pragma unroll
    for (int o = 16; o > 0; o >>= 1) s += __shfl_xor_sync(0xFFFFFFFFu, s, o);
    if (lane == 0) {
        float c = fmaxf(s, EPS_F);
        g_fac[f] = (c > EPS_F) ? (1.0f / c) : 0.0f;
    }
}

// ---------------------------------------------------------------------------
// Prep kernel 2 (fused): blocks 0-127 compute M row f and write fp16 hi/lo
// split directly (Mt layout [g][f]); block 128 computes b2.
// ---------------------------------------------------------------------------
__global__ void prep_Msplit_kernel(const float* __restrict__ graph,
                                   const float* __restrict__ W,
                                   const float* __restrict__ b) {
    int g = threadIdx.x;
    if (blockIdx.x < KD) {
        int f = blockIdx.x;
        float s = 0.0f;
        #pragma unroll 8
        for (int k = 0; k < KD; k++)
            s = fmaf(W[k * KD + f], graph[k * ND + g] * g_fac[k], s);
        __half hi = __float2half(s);
        g_Bhi[g * KD + f] = hi;
        g_Blo[g * KD + f] = __float2half(s - __half2float(hi));
    } else {
        float s2 = 0.0f;
        #pragma unroll 8
        for (int k = 0; k < KD; k++)
            s2 = fmaf(b[k], graph[k * ND + g] * g_fac[k], s2);
        g_b2[g] = s2;
    }
}

// ---------------------------------------------------------------------------
// Main persistent kernel.
//   Warps 0-7 : compute; warp w owns rows (w>>1)*32..+32, cols (w&1)*64..+64.
//               2 MMA warps/SMSP. A fp16 single; B fp16 hi + lo (2 passes).
//               B fragments via ldmatrix.x4 (2 n-blocks x 2 k-halves per op).
//   Warps 8-11: producer; 8-deep LDG.128 batches -> fp16 -> smem.
// ---------------------------------------------------------------------------
__global__ void __launch_bounds__(NTHREADS, 1)
mp_mma_kernel(const float* __restrict__ h, float* __restrict__ out) {
    extern __shared__ char smem[];
    const uint32_t sb = smem_u32(smem);
    const int tid = threadIdx.x, wid = tid >> 5, lane = tid & 31;
    const int bid = blockIdx.x;

    // --- init: B (Mt hi/lo) into padded smem, b2, mbarriers ---
    {
        const uint32_t* bh = (const uint32_t*)g_Bhi;
        const uint32_t* bl = (const uint32_t*)g_Blo;
        for (int w = tid; w < 8192; w += NTHREADS) {     // uint32 index (2 fp16)
            int row = w >> 6, cb = (w & 63) * 4;
            *(uint32_t*)(smem + SB_HI + row * ROWB + cb) = bh[w];
            *(uint32_t*)(smem + SB_LO + row * ROWB + cb) = bl[w];
        }
        if (tid < ND) *(float*)(smem + SB2 + tid * 4) = g_b2[tid];
        if (tid == 0) {
            MBAR_INIT(sb + MB_OFF + 0, 128);   // full[0]  (128 producer threads)
            MBAR_INIT(sb + MB_OFF + 8, 128);   // full[1]
            MBAR_INIT(sb + MB_OFF + 16, 256);  // free[0]  (256 consumer threads)
            MBAR_INIT(sb + MB_OFF + 24, 256);  // free[1]
        }
    }
    __syncthreads();

    const int nt = (NTILES - bid + NSM - 1) / NSM;   // 13 or 14 tiles

    if (wid >= 8) {
        // ================= producer warps (4): 8-deep LDG batches =================
        const int wt = tid - 256;
        for (int it = 0; it < nt; ++it) {
            const int p = it & 1, ph = (it >> 1) & 1;
            if (it >= 2) MBAR_WAIT(sb + MB_OFF + 16 + 8 * p, ph ^ 1);
            const float4* hg = (const float4*)h + (size_t)(bid + it * NSM) * 4096;
            char* aB = smem + SA0 + p * SA_STRIDE;
            #pragma unroll
            for (int phs = 0; phs < 4; phs++) {
                float4 x[8];
                #pragma unroll
                for (int i = 0; i < 8; i++) x[i] = hg[wt + 128 * (phs * 8 + i)];
                #pragma unroll
                for (int i = 0; i < 8; i++) {
                    int v = wt + 128 * (phs * 8 + i);
                    int row = v >> 5, cb = (v & 31) * 8;     // 4 fp16 = 8 B
                    __half2 p01 = __floats2half2_rn(x[i].x, x[i].y);
                    __half2 p23 = __floats2half2_rn(x[i].z, x[i].w);
                    *(uint2*)(aB + row * ROWB + cb) =
                        make_uint2(*(uint32_t*)&p01, *(uint32_t*)&p23);
                }
            }
            MBAR_ARRIVE(sb + MB_OFF + 8 * p);
        }
    } else {
        // ================= compute warps (8) =================
        const int mrow = (wid >> 1) * 32;            // row quadrant base
        const int ncol = (wid & 1) * 64;             // col quadrant base
        const int lm = lane >> 3, lr = lane & 7;
        const uint32_t aOff = (uint32_t)(((lm & 1) * 8 + lr) * ROWB + (lm >> 1) * 16);
        // X4 B mapping: matrix q -> (nblock q>>1 at +8*ROWB, khalf q&1 at +16B)
        const uint32_t bOff4 = (uint32_t)(lr * ROWB + (lm & 1) * 16 + (lm >> 1) * 8 * ROWB);
        const uint32_t bHiBase = sb + SB_HI + ncol * ROWB + bOff4;
        const uint32_t bLoBase = sb + SB_LO + ncol * ROWB + bOff4;

        for (int it = 0; it < nt; ++it) {
            const int p = it & 1, ph = (it >> 1) & 1;
            MBAR_WAIT(sb + MB_OFF + 8 * p, ph);

            const uint32_t aB = sb + SA0 + p * SA_STRIDE + mrow * ROWB + aOff;

            float acc[2][8][4];
            #pragma unroll
            for (int mt = 0; mt < 2; mt++)
                #pragma unroll
                for (int n = 0; n < 8; n++)
                    #pragma unroll
                    for (int q = 0; q < 4; q++) acc[mt][n][q] = 0.0f;

            #pragma unroll 1
            for (int ks = 0; ks < 8; ks++) {
                const uint32_t koff = ks * 32;       // 16 fp16 = 32 B
                uint32_t a0[4], a1[4];
                LDSM_X4(a0, aB + koff);
                LDSM_X4(a1, aB + 16 * ROWB + koff);
                #pragma unroll
                for (int n4 = 0; n4 < 4; n4++) {
                    uint32_t bh[4], bl[4];
                    LDSM_X4(bh, bHiBase + n4 * 16 * ROWB + koff);
                    LDSM_X4(bl, bLoBase + n4 * 16 * ROWB + koff);
                    mma_f16(acc[0][2 * n4 + 0], a0, bh[0], bh[1]);
                    mma_f16(acc[1][2 * n4 + 0], a1, bh[0], bh[1]);
                    mma_f16(acc[0][2 * n4 + 1], a0, bh[2], bh[3]);
                    mma_f16(acc[1][2 * n4 + 1], a1, bh[2], bh[3]);
                    mma_f16(acc[0][2 * n4 + 0], a0, bl[0], bl[1]);
                    mma_f16(acc[1][2 * n4 + 0], a1, bl[0], bl[1]);
                    mma_f16(acc[0][2 * n4 + 1], a0, bl[2], bl[3]);
                    mma_f16(acc[1][2 * n4 + 1], a1, bl[2], bl[3]);
                }
            }
            MBAR_ARRIVE(sb + MB_OFF + 16 + 8 * p);   // buffer free (results in regs)

            // epilogue: + b2, direct STG
            float2 bb[8];
            #pragma unroll
            for (int n = 0; n < 8; n++)
                bb[n] = *(const float2*)(smem + SB2 + (ncol + n * 8 + (lane & 3) * 2) * 4);
            const size_t tile = (size_t)(bid + it * NSM);
            #pragma unroll
            for (int mt = 0; mt < 2; mt++) {
                size_t r0 = tile * 128 + mrow + mt * 16 + (lane >> 2);
                float* o = out + r0 * ND + ncol + (lane & 3) * 2;
                #pragma unroll
                for (int n = 0; n < 8; n++) {
                    *(float2*)(o + n * 8) =
                        make_float2(acc[mt][n][0] + bb[n].x, acc[mt][n][1] + bb[n].y);
                    *(float2*)(o + 8 * ND + n * 8) =
                        make_float2(acc[mt][n][2] + bb[n].x, acc[mt][n][3] + bb[n].y);
                }
            }
        }
    }
}

// ---------------------------------------------------------------------------
// Launch
// ---------------------------------------------------------------------------
extern "C" void kernel_launch(void* const* d_in, const int* in_sizes, int n_in,
                              void* d_out, int out_size) {
    (void)in_sizes; (void)n_in; (void)out_size;
    const float* h     = (const float*)d_in[0];
    const float* graph = (const float*)d_in[1];
    const float* W     = (const float*)d_in[2];
    const float* b     = (const float*)d_in[3];
    float* out         = (float*)d_out;

    cudaFuncSetAttribute(mp_mma_kernel,
                         cudaFuncAttributeMaxDynamicSharedMemorySize, SMEM_TOTAL);

    prep_fac_kernel<<<KD, 32>>>(graph);
    prep_Msplit_kernel<<<KD + 1, ND>>>(graph, W, b);
    mp_mma_kernel<<<NSM, NTHREADS, SMEM_TOTAL>>>(h, out);
}